// round 13
// baseline (speedup 1.0000x reference)
#include <cuda_runtime.h>
#include <cuda_bf16.h>
#include <cstdint>

#define N_NODES 50000
#define N_EDGES 800000
#define DIM 128
#define NL 3
#define PAD 64    // max degree slack: P(Poisson(16) >= 64) ~ 1e-19 per node
#define STR 136   // padded bf16 row stride (conflict-free fragment LDS)

typedef unsigned long long u64;
typedef unsigned int u32;
typedef unsigned short us;

// Scratch (allocation-free rule: __device__ globals)
__device__ float g_h[(size_t)N_NODES * DIM];        // h = z + neighbor sum
__device__ float g_z[(size_t)N_NODES * DIM];        // inter-layer activations
__device__ int   g_cnt[N_NODES];                    // per-dst degree counter
__device__ int   g_srcs[(size_t)N_NODES * PAD];     // padded CSR adjacency
__device__ int   g_is64;
// Padded [n][k] bf16 images of W^T (hi/lo split), 6 matrices (3 layers x 2)
__device__ us g_Wimg_hi[6 * DIM * STR];
__device__ us g_Wimg_lo[6 * DIM * STR];

__device__ __forceinline__ void bsplit(float v, us& h, us& l) {
    __nv_bfloat16 bh = __float2bfloat16(v);
    float r = v - __bfloat162float(bh);
    __nv_bfloat16 bl = __float2bfloat16(r);
    h = __bfloat16_as_ushort(bh);
    l = __bfloat16_as_ushort(bl);
}

// mma.sync m16n8k16 row.col f32.bf16.bf16.f32 (sm_80+ PTX, tensor pipe)
__device__ __forceinline__ void mma16816(float c[4], const u32 a[4], u32 b0, u32 b1) {
    asm volatile(
        "mma.sync.aligned.m16n8k16.row.col.f32.bf16.bf16.f32 "
        "{%0,%1,%2,%3}, {%4,%5,%6,%7}, {%8,%9}, {%0,%1,%2,%3};"
        : "+f"(c[0]), "+f"(c[1]), "+f"(c[2]), "+f"(c[3])
        : "r"(a[0]), "r"(a[1]), "r"(a[2]), "r"(a[3]), "r"(b0), "r"(b1));
}

// ---------------------------------------------------------------------------
// Graph preprocessing
// ---------------------------------------------------------------------------
// Parallel int64/int32 detect: one warp, ballot (replaces serial 64-load chain)
__global__ void detect_idx_kernel(const int* __restrict__ ei_i32) {
    const int lane = threadIdx.x;  // 32
    int bad = (ei_i32[2 * lane + 1] != 0) | (ei_i32[2 * (lane + 32) + 1] != 0);
    unsigned m = __ballot_sync(0xffffffffu, bad);
    if (lane == 0) g_is64 = (m == 0);
}

__global__ void zero_cnt_kernel() {
    int i = blockIdx.x * blockDim.x + threadIdx.x;
    if (i < N_NODES) g_cnt[i] = 0;
}

__global__ void fill_kernel(const void* __restrict__ ei) {
    int e = blockIdx.x * blockDim.x + threadIdx.x;
    if (e >= N_EDGES) return;
    int s, d;
    if (g_is64) {
        const long long* p = (const long long*)ei;
        s = (int)p[e];
        d = (int)p[N_EDGES + e];
    } else {
        const int* p = (const int*)ei;
        s = p[e];
        d = p[N_EDGES + e];
    }
    int slot = atomicAdd(&g_cnt[d], 1);
    if (slot < PAD) g_srcs[(size_t)d * PAD + slot] = s;
}

// Build padded bf16 hi/lo images of W^T: img[n][k] = W[k][n].
// 96 blocks: mat = blockIdx>>4 (0..5), chunk = blockIdx&15.
__global__ void convert_w_kernel(const float* __restrict__ Ws1,
                                 const float* __restrict__ Ws2) {
    const int mat = blockIdx.x >> 4;
    const int chunk = blockIdx.x & 15;
    const float* W = ((mat & 1) ? Ws2 : Ws1) + (size_t)(mat >> 1) * DIM * DIM;
    us* hi = g_Wimg_hi + (size_t)mat * DIM * STR;
    us* lo = g_Wimg_lo + (size_t)mat * DIM * STR;
    int idx = chunk * 1024 + threadIdx.x;   // 256 threads x 4 iters = 1024
#pragma unroll
    for (int it = 0; it < 4; it++, idx += 256) {
        const int n = idx >> 7, k = idx & 127;
        us h, l;
        bsplit(W[k * DIM + n], h, l);
        hi[n * STR + k] = h;
        lo[n * STR + k] = l;
    }
}

// ---------------------------------------------------------------------------
// Aggregation: warp per node, h[n] = z[n] + sum_{s in adj(n)} z[s].
// 8-deep edge unroll (mean deg 16): more MLP to cover L2 latency.
// ---------------------------------------------------------------------------
__global__ void aggregate_kernel(const float* __restrict__ z,
                                 float* __restrict__ h) {
    const int w = (blockIdx.x * blockDim.x + threadIdx.x) >> 5;
    if (w >= N_NODES) return;
    const int lane = threadIdx.x & 31;
    const float* zp = z + lane * 4;

    const int* adj = g_srcs + (size_t)w * PAD;
    int deg = g_cnt[w];
    if (deg > PAD) deg = PAD;

    float4 acc = *(const float4*)(zp + (size_t)w * DIM);  // self term
    int e = 0;
    for (; e + 8 <= deg; e += 8) {
        int s[8];
#pragma unroll
        for (int j = 0; j < 8; j++) s[j] = adj[e + j];
        float4 v[8];
#pragma unroll
        for (int j = 0; j < 8; j++) v[j] = *(const float4*)(zp + (size_t)s[j] * DIM);
        acc.x += ((v[0].x + v[1].x) + (v[2].x + v[3].x)) + ((v[4].x + v[5].x) + (v[6].x + v[7].x));
        acc.y += ((v[0].y + v[1].y) + (v[2].y + v[3].y)) + ((v[4].y + v[5].y) + (v[6].y + v[7].y));
        acc.z += ((v[0].z + v[1].z) + (v[2].z + v[3].z)) + ((v[4].z + v[5].z) + (v[6].z + v[7].z));
        acc.w += ((v[0].w + v[1].w) + (v[2].w + v[3].w)) + ((v[4].w + v[5].w) + (v[6].w + v[7].w));
    }
    if (e + 4 <= deg) {
        const int s0 = adj[e], s1 = adj[e + 1], s2 = adj[e + 2], s3 = adj[e + 3];
        const float4 v0 = *(const float4*)(zp + (size_t)s0 * DIM);
        const float4 v1 = *(const float4*)(zp + (size_t)s1 * DIM);
        const float4 v2 = *(const float4*)(zp + (size_t)s2 * DIM);
        const float4 v3 = *(const float4*)(zp + (size_t)s3 * DIM);
        acc.x += (v0.x + v1.x) + (v2.x + v3.x);
        acc.y += (v0.y + v1.y) + (v2.y + v3.y);
        acc.z += (v0.z + v1.z) + (v2.z + v3.z);
        acc.w += (v0.w + v1.w) + (v2.w + v3.w);
        e += 4;
    }
    for (; e < deg; e++) {
        const float4 v = *(const float4*)(zp + (size_t)adj[e] * DIM);
        acc.x += v.x; acc.y += v.y; acc.z += v.z; acc.w += v.w;
    }
    *(float4*)(h + (size_t)w * DIM + lane * 4) = acc;
}

// ---------------------------------------------------------------------------
// Fused per-layer MLP: z = relu(relu(h@W1+b1)@W2+b2) for a 128-row tile.
// bf16x3 split precision per GEMM (D = Ah*Wh + Ah*Wl + Al*Wh, fp32 acc).
// t never leaves the CTA: after MMA1, relu(t) is split to bf16 and written
// back over the A-tile smem, then MMA2 runs. 8 warps (4m x 2n).
// ---------------------------------------------------------------------------
#define SMEM_LAYER (6 * 128 * STR * 2)   // 208896 B

__device__ __forceinline__ void mma_mainloop(const us* sAh, const us* sAl,
                                             const us* sWh, const us* sWl,
                                             int wm, int wn, int g, int t,
                                             float acc[2][8][4]) {
#pragma unroll
    for (int ks = 0; ks < 8; ks++) {
        const int k0 = ks * 16;
        u32 ah[2][4], al[2][4];
#pragma unroll
        for (int mt = 0; mt < 2; mt++) {
            const int base = (wm * 32 + mt * 16 + g) * STR + k0 + t * 2;
            ah[mt][0] = *(const u32*)(sAh + base);
            ah[mt][1] = *(const u32*)(sAh + base + 8 * STR);
            ah[mt][2] = *(const u32*)(sAh + base + 8);
            ah[mt][3] = *(const u32*)(sAh + base + 8 * STR + 8);
            al[mt][0] = *(const u32*)(sAl + base);
            al[mt][1] = *(const u32*)(sAl + base + 8 * STR);
            al[mt][2] = *(const u32*)(sAl + base + 8);
            al[mt][3] = *(const u32*)(sAl + base + 8 * STR + 8);
        }
#pragma unroll
        for (int nt = 0; nt < 8; nt++) {
            const int bbase = (wn * 64 + nt * 8 + g) * STR + k0 + t * 2;
            const u32 bh0 = *(const u32*)(sWh + bbase);
            const u32 bh1 = *(const u32*)(sWh + bbase + 8);
            const u32 bl0 = *(const u32*)(sWl + bbase);
            const u32 bl1 = *(const u32*)(sWl + bbase + 8);
#pragma unroll
            for (int mt = 0; mt < 2; mt++) {
                mma16816(acc[mt][nt], ah[mt], bh0, bh1);
                mma16816(acc[mt][nt], ah[mt], bl0, bl1);
                mma16816(acc[mt][nt], al[mt], bh0, bh1);
            }
        }
    }
}

__global__ __launch_bounds__(256, 1)
void layer_kernel(const float* __restrict__ A, int layer,
                  const float* __restrict__ b1, const float* __restrict__ b2,
                  float* __restrict__ C) {
    extern __shared__ char smem[];
    us* sAh  = (us*)smem;                // [128][STR] each
    us* sAl  = sAh + 128 * STR;
    us* sW1h = sAl + 128 * STR;
    us* sW1l = sW1h + 128 * STR;
    us* sW2h = sW1l + 128 * STR;
    us* sW2l = sW2h + 128 * STR;

    const int tid = threadIdx.x;   // 256
    const int wid = tid >> 5, lane = tid & 31;
    const int m0 = blockIdx.x * 128;

    // Copy 4 padded W^T images (34816B each) linearly, fully coalesced.
    {
        const int mat1 = 2 * layer, mat2 = 2 * layer + 1;
        const uint4* w1h = (const uint4*)(g_Wimg_hi + (size_t)mat1 * DIM * STR);
        const uint4* w1l = (const uint4*)(g_Wimg_lo + (size_t)mat1 * DIM * STR);
        const uint4* w2h = (const uint4*)(g_Wimg_hi + (size_t)mat2 * DIM * STR);
        const uint4* w2l = (const uint4*)(g_Wimg_lo + (size_t)mat2 * DIM * STR);
        uint4* d1h = (uint4*)sW1h;
        uint4* d1l = (uint4*)sW1l;
        uint4* d2h = (uint4*)sW2h;
        uint4* d2l = (uint4*)sW2l;
        const int n16 = 128 * STR / 8;   // 2176 uint4
        for (int i = tid; i < n16; i += 256) {
            d1h[i] = w1h[i]; d1l[i] = w1l[i];
            d2h[i] = w2h[i]; d2l[i] = w2l[i];
        }
    }
    // Stage A tile: load fp32, split to bf16 hi/lo, store padded rows.
    {
#pragma unroll
        for (int it = 0; it < 16; it++) {
            const int i = tid + it * 256;        // 0..4095 float4s
            const int m = i >> 5, q = i & 31;    // k0 = q*4
            const int gm = m0 + m;
            float4 v = make_float4(0.f, 0.f, 0.f, 0.f);
            if (gm < N_NODES) v = *(const float4*)(A + (size_t)gm * DIM + q * 4);
            us h0, h1, h2, h3, l0, l1, l2, l3;
            bsplit(v.x, h0, l0); bsplit(v.y, h1, l1);
            bsplit(v.z, h2, l2); bsplit(v.w, h3, l3);
            const int off = m * STR + q * 4;
            *(uint2*)(sAh + off) = make_uint2((u32)h0 | ((u32)h1 << 16),
                                              (u32)h2 | ((u32)h3 << 16));
            *(uint2*)(sAl + off) = make_uint2((u32)l0 | ((u32)l1 << 16),
                                              (u32)l2 | ((u32)l3 << 16));
        }
    }
    __syncthreads();

    const int wm = wid & 3;    // 32-row group
    const int wn = wid >> 2;   // 64-col group
    const int g = lane >> 2, t = lane & 3;

    float acc[2][8][4];
#pragma unroll
    for (int mt = 0; mt < 2; mt++)
#pragma unroll
        for (int nt = 0; nt < 8; nt++)
#pragma unroll
            for (int r = 0; r < 4; r++) acc[mt][nt][r] = 0.f;

    // ---- GEMM 1: t = relu(A @ W1 + b1) ----
    mma_mainloop(sAh, sAl, sW1h, sW1l, wm, wn, g, t, acc);
    __syncthreads();   // everyone done reading sAh/sAl

    // Write relu(t) split-bf16 back over the A tile (conflict-free u32 stores)
#pragma unroll
    for (int nt = 0; nt < 8; nt++) {
        const int col = wn * 64 + nt * 8 + t * 2;
        const float2 bb = *(const float2*)(b1 + col);
#pragma unroll
        for (int mt = 0; mt < 2; mt++) {
            const int row0 = wm * 32 + mt * 16 + g;
            const float v0 = fmaxf(acc[mt][nt][0] + bb.x, 0.f);
            const float v1 = fmaxf(acc[mt][nt][1] + bb.y, 0.f);
            const float v2 = fmaxf(acc[mt][nt][2] + bb.x, 0.f);
            const float v3 = fmaxf(acc[mt][nt][3] + bb.y, 0.f);
            us h0, l0, h1, l1, h2, l2, h3, l3;
            bsplit(v0, h0, l0); bsplit(v1, h1, l1);
            bsplit(v2, h2, l2); bsplit(v3, h3, l3);
            *(u32*)(sAh + row0 * STR + col) = (u32)h0 | ((u32)h1 << 16);
            *(u32*)(sAl + row0 * STR + col) = (u32)l0 | ((u32)l1 << 16);
            *(u32*)(sAh + (row0 + 8) * STR + col) = (u32)h2 | ((u32)h3 << 16);
            *(u32*)(sAl + (row0 + 8) * STR + col) = (u32)l2 | ((u32)l3 << 16);
        }
    }
    __syncthreads();

#pragma unroll
    for (int mt = 0; mt < 2; mt++)
#pragma unroll
        for (int nt = 0; nt < 8; nt++)
#pragma unroll
            for (int r = 0; r < 4; r++) acc[mt][nt][r] = 0.f;

    // ---- GEMM 2: z = relu(t @ W2 + b2) ----
    mma_mainloop(sAh, sAl, sW2h, sW2l, wm, wn, g, t, acc);

    // Final epilogue: bias + relu, direct global stores.
#pragma unroll
    for (int nt = 0; nt < 8; nt++) {
        const int col = wn * 64 + nt * 8 + t * 2;
        const float2 bb = *(const float2*)(b2 + col);
#pragma unroll
        for (int mt = 0; mt < 2; mt++) {
            const int row0 = m0 + wm * 32 + mt * 16 + g;
            if (row0 < N_NODES) {
                float2 o;
                o.x = fmaxf(acc[mt][nt][0] + bb.x, 0.f);
                o.y = fmaxf(acc[mt][nt][1] + bb.y, 0.f);
                *(float2*)(C + (size_t)row0 * DIM + col) = o;
            }
            const int row1 = row0 + 8;
            if (row1 < N_NODES) {
                float2 o;
                o.x = fmaxf(acc[mt][nt][2] + bb.x, 0.f);
                o.y = fmaxf(acc[mt][nt][3] + bb.y, 0.f);
                *(float2*)(C + (size_t)row1 * DIM + col) = o;
            }
        }
    }
}

extern "C" void kernel_launch(void* const* d_in, const int* in_sizes, int n_in,
                              void* d_out, int out_size) {
    const float* x   = (const float*)d_in[0];
    const float* Ws1 = (const float*)d_in[1];
    const float* bs1 = (const float*)d_in[2];
    const float* Ws2 = (const float*)d_in[3];
    const float* bs2 = (const float*)d_in[4];
    const void*  ei  = d_in[5];
    float* out = (float*)d_out;

    cudaFuncSetAttribute(layer_kernel, cudaFuncAttributeMaxDynamicSharedMemorySize,
                         SMEM_LAYER);

    float *h_buf, *z_buf;
    cudaGetSymbolAddress((void**)&h_buf, g_h);
    cudaGetSymbolAddress((void**)&z_buf, g_z);

    const int edge_blocks = (N_EDGES + 255) / 256;          // 3125
    const int tile_blocks = (N_NODES + 127) / 128;          // 391
    const int agg_blocks  = (N_NODES * 32 + 255) / 256;     // 6250

    // One-time preprocessing (edge_index and W reused by all layers)
    detect_idx_kernel<<<1, 32>>>((const int*)ei);
    zero_cnt_kernel<<<(N_NODES + 255) / 256, 256>>>();
    fill_kernel<<<edge_blocks, 256>>>(ei);
    convert_w_kernel<<<96, 256>>>(Ws1, Ws2);

    const float* zcur = x;
    for (int l = 0; l < NL; l++) {
        aggregate_kernel<<<agg_blocks, 256>>>(zcur, h_buf);
        float* zout = (l == NL - 1) ? out : z_buf;
        layer_kernel<<<tile_blocks, 256, SMEM_LAYER>>>(
            h_buf, l, bs1 + (size_t)l * DIM, bs2 + (size_t)l * DIM, zout);
        zcur = zout;
    }
}

// round 14
// speedup vs baseline: 1.2298x; 1.2298x over previous
#include <cuda_runtime.h>
#include <cuda_bf16.h>
#include <cstdint>

#define N_NODES 50000
#define N_EDGES 800000
#define DIM 128
#define NL 3
#define PAD 64    // max degree slack: P(Poisson(16) >= 64) ~ 1e-19 per node
#define STR 136   // padded bf16 row stride (136*2=272B -> conflict-free frags)

typedef unsigned long long u64;
typedef unsigned int u32;
typedef unsigned short us;

// Scratch (allocation-free rule: __device__ globals)
__device__ float g_h[(size_t)N_NODES * DIM];        // h = z + neighbor sum
__device__ float g_t[(size_t)N_NODES * DIM];        // t = relu(h@W1 + b1)
__device__ float g_z[(size_t)N_NODES * DIM];        // z = relu(t@W2 + b2)
__device__ int   g_cnt[N_NODES];                    // per-dst degree counter
__device__ int   g_srcs[(size_t)N_NODES * PAD];     // padded CSR adjacency
__device__ int   g_is64;
// Padded [n][k] bf16 images of W^T (hi/lo split), 6 matrices (3 layers x 2)
__device__ us g_Wimg_hi[6 * DIM * STR];
__device__ us g_Wimg_lo[6 * DIM * STR];

__device__ __forceinline__ void bsplit(float v, us& h, us& l) {
    __nv_bfloat16 bh = __float2bfloat16(v);
    float r = v - __bfloat162float(bh);
    __nv_bfloat16 bl = __float2bfloat16(r);
    h = __bfloat16_as_ushort(bh);
    l = __bfloat16_as_ushort(bl);
}

// mma.sync m16n8k16 row.col f32.bf16.bf16.f32 (sm_80+ PTX, tensor pipe)
__device__ __forceinline__ void mma16816(float c[4], const u32 a[4], u32 b0, u32 b1) {
    asm volatile(
        "mma.sync.aligned.m16n8k16.row.col.f32.bf16.bf16.f32 "
        "{%0,%1,%2,%3}, {%4,%5,%6,%7}, {%8,%9}, {%0,%1,%2,%3};"
        : "+f"(c[0]), "+f"(c[1]), "+f"(c[2]), "+f"(c[3])
        : "r"(a[0]), "r"(a[1]), "r"(a[2]), "r"(a[3]), "r"(b0), "r"(b1));
}

// ---------------------------------------------------------------------------
// Graph preprocessing
// ---------------------------------------------------------------------------
// Parallel int64/int32 detect: one warp, ballot (replaces serial 64-load chain)
__global__ void detect_idx_kernel(const int* __restrict__ ei_i32) {
    const int lane = threadIdx.x;  // 32
    int bad = (ei_i32[2 * lane + 1] != 0) | (ei_i32[2 * (lane + 32) + 1] != 0);
    unsigned m = __ballot_sync(0xffffffffu, bad);
    if (lane == 0) g_is64 = (m == 0);
}

__global__ void zero_cnt_kernel() {
    int i = blockIdx.x * blockDim.x + threadIdx.x;
    if (i < N_NODES) g_cnt[i] = 0;
}

__global__ void fill_kernel(const void* __restrict__ ei) {
    int e = blockIdx.x * blockDim.x + threadIdx.x;
    if (e >= N_EDGES) return;
    int s, d;
    if (g_is64) {
        const long long* p = (const long long*)ei;
        s = (int)p[e];
        d = (int)p[N_EDGES + e];
    } else {
        const int* p = (const int*)ei;
        s = p[e];
        d = p[N_EDGES + e];
    }
    int slot = atomicAdd(&g_cnt[d], 1);
    if (slot < PAD) g_srcs[(size_t)d * PAD + slot] = s;
}

// Build padded bf16 hi/lo images of W^T: img[n][k] = W[k][n].
// 96 blocks: mat = blockIdx>>4 (0..5), chunk = blockIdx&15.
__global__ void convert_w_kernel(const float* __restrict__ Ws1,
                                 const float* __restrict__ Ws2) {
    const int mat = blockIdx.x >> 4;
    const int chunk = blockIdx.x & 15;
    const float* W = ((mat & 1) ? Ws2 : Ws1) + (size_t)(mat >> 1) * DIM * DIM;
    us* hi = g_Wimg_hi + (size_t)mat * DIM * STR;
    us* lo = g_Wimg_lo + (size_t)mat * DIM * STR;
    int idx = chunk * 1024 + threadIdx.x;   // 256 threads x 4 iters = 1024
#pragma unroll
    for (int it = 0; it < 4; it++, idx += 256) {
        const int n = idx >> 7, k = idx & 127;
        us h, l;
        bsplit(W[k * DIM + n], h, l);
        hi[n * STR + k] = h;
        lo[n * STR + k] = l;
    }
}

// ---------------------------------------------------------------------------
// Aggregation: warp per node, h[n] = z[n] + sum_{s in adj(n)} z[s].
// 4-deep edge unroll (measured-good config from round 8).
// ---------------------------------------------------------------------------
__global__ void aggregate_kernel(const float* __restrict__ z,
                                 float* __restrict__ h) {
    const int w = (blockIdx.x * blockDim.x + threadIdx.x) >> 5;
    if (w >= N_NODES) return;
    const int lane = threadIdx.x & 31;
    const float* zp = z + lane * 4;

    const int* adj = g_srcs + (size_t)w * PAD;
    int deg = g_cnt[w];
    if (deg > PAD) deg = PAD;

    float4 acc = *(const float4*)(zp + (size_t)w * DIM);  // self term
    int e = 0;
    for (; e + 4 <= deg; e += 4) {
        const int s0 = adj[e], s1 = adj[e + 1];
        const int s2 = adj[e + 2], s3 = adj[e + 3];
        const float4 v0 = *(const float4*)(zp + (size_t)s0 * DIM);
        const float4 v1 = *(const float4*)(zp + (size_t)s1 * DIM);
        const float4 v2 = *(const float4*)(zp + (size_t)s2 * DIM);
        const float4 v3 = *(const float4*)(zp + (size_t)s3 * DIM);
        acc.x += (v0.x + v1.x) + (v2.x + v3.x);
        acc.y += (v0.y + v1.y) + (v2.y + v3.y);
        acc.z += (v0.z + v1.z) + (v2.z + v3.z);
        acc.w += (v0.w + v1.w) + (v2.w + v3.w);
    }
    for (; e < deg; e++) {
        const float4 v = *(const float4*)(zp + (size_t)adj[e] * DIM);
        acc.x += v.x; acc.y += v.y; acc.z += v.z; acc.w += v.w;
    }
    *(float4*)(h + (size_t)w * DIM + lane * 4) = acc;
}

// ---------------------------------------------------------------------------
// Tensor-pipe GEMM via mma.sync (bf16x3 split precision):
// C = relu(A @ W + bias), tile 128x128, full K=128.
// D = Ah*Wh + Ah*Wl + Al*Wh, fp32 accumulate -> rel err ~1e-5.
// 8 warps (4m x 2n); warp = 32x64 = 2x8 m16n8k16 tiles.
// ---------------------------------------------------------------------------
#define SMEM_GEMM (4 * 128 * STR * 2)   // Ah, Al, Wh, Wl = 139264 B

__global__ __launch_bounds__(256, 1)
void gemm_mma(const float* __restrict__ A, int mat,
              const float* __restrict__ bias, float* __restrict__ C) {
    extern __shared__ char smem[];
    us* sAh = (us*)smem;                 // [128][STR]
    us* sAl = sAh + 128 * STR;
    us* sWh = sAl + 128 * STR;
    us* sWl = sWh + 128 * STR;

    const int tid = threadIdx.x;   // 256
    const int wid = tid >> 5, lane = tid & 31;
    const int m0 = blockIdx.x * 128;

    // Copy padded W^T images (34816B each) linearly, fully coalesced.
    {
        const uint4* wh = (const uint4*)(g_Wimg_hi + (size_t)mat * DIM * STR);
        const uint4* wl = (const uint4*)(g_Wimg_lo + (size_t)mat * DIM * STR);
        uint4* dh = (uint4*)sWh;
        uint4* dl = (uint4*)sWl;
        const int n16 = 128 * STR / 8;   // 2176 uint4
        for (int i = tid; i < n16; i += 256) { dh[i] = wh[i]; dl[i] = wl[i]; }
    }
    // Stage A tile: load fp32, split to bf16 hi/lo, store padded rows.
    {
#pragma unroll
        for (int it = 0; it < 16; it++) {
            const int i = tid + it * 256;        // 0..4095 float4s
            const int m = i >> 5, q = i & 31;    // k0 = q*4
            const int gm = m0 + m;
            float4 v = make_float4(0.f, 0.f, 0.f, 0.f);
            if (gm < N_NODES) v = *(const float4*)(A + (size_t)gm * DIM + q * 4);
            us h0, h1, h2, h3, l0, l1, l2, l3;
            bsplit(v.x, h0, l0); bsplit(v.y, h1, l1);
            bsplit(v.z, h2, l2); bsplit(v.w, h3, l3);
            const int off = m * STR + q * 4;
            *(uint2*)(sAh + off) = make_uint2((u32)h0 | ((u32)h1 << 16),
                                              (u32)h2 | ((u32)h3 << 16));
            *(uint2*)(sAl + off) = make_uint2((u32)l0 | ((u32)l1 << 16),
                                              (u32)l2 | ((u32)l3 << 16));
        }
    }
    __syncthreads();

    const int wm = wid & 3;    // 32-row group
    const int wn = wid >> 2;   // 64-col group
    const int g = lane >> 2, t = lane & 3;

    float acc[2][8][4];
#pragma unroll
    for (int mt = 0; mt < 2; mt++)
#pragma unroll
        for (int nt = 0; nt < 8; nt++)
#pragma unroll
            for (int r = 0; r < 4; r++) acc[mt][nt][r] = 0.f;

#pragma unroll
    for (int ks = 0; ks < 8; ks++) {
        const int k0 = ks * 16;
        u32 ah[2][4], al[2][4];
#pragma unroll
        for (int mt = 0; mt < 2; mt++) {
            const int base = (wm * 32 + mt * 16 + g) * STR + k0 + t * 2;
            ah[mt][0] = *(const u32*)(sAh + base);
            ah[mt][1] = *(const u32*)(sAh + base + 8 * STR);
            ah[mt][2] = *(const u32*)(sAh + base + 8);
            ah[mt][3] = *(const u32*)(sAh + base + 8 * STR + 8);
            al[mt][0] = *(const u32*)(sAl + base);
            al[mt][1] = *(const u32*)(sAl + base + 8 * STR);
            al[mt][2] = *(const u32*)(sAl + base + 8);
            al[mt][3] = *(const u32*)(sAl + base + 8 * STR + 8);
        }
#pragma unroll
        for (int nt = 0; nt < 8; nt++) {
            const int bbase = (wn * 64 + nt * 8 + g) * STR + k0 + t * 2;
            const u32 bh0 = *(const u32*)(sWh + bbase);
            const u32 bh1 = *(const u32*)(sWh + bbase + 8);
            const u32 bl0 = *(const u32*)(sWl + bbase);
            const u32 bl1 = *(const u32*)(sWl + bbase + 8);
#pragma unroll
            for (int mt = 0; mt < 2; mt++) {
                mma16816(acc[mt][nt], ah[mt], bh0, bh1);
                mma16816(acc[mt][nt], ah[mt], bl0, bl1);
                mma16816(acc[mt][nt], al[mt], bh0, bh1);
            }
        }
    }

    // Epilogue: bias + relu, direct global stores (float2 per fragment row).
#pragma unroll
    for (int nt = 0; nt < 8; nt++) {
        const int col = wn * 64 + nt * 8 + t * 2;
        const float b0 = bias[col], b1 = bias[col + 1];
#pragma unroll
        for (int mt = 0; mt < 2; mt++) {
            const int row0 = m0 + wm * 32 + mt * 16 + g;
            if (row0 < N_NODES) {
                float2 o;
                o.x = fmaxf(acc[mt][nt][0] + b0, 0.f);
                o.y = fmaxf(acc[mt][nt][1] + b1, 0.f);
                *(float2*)(C + (size_t)row0 * DIM + col) = o;
            }
            const int row1 = row0 + 8;
            if (row1 < N_NODES) {
                float2 o;
                o.x = fmaxf(acc[mt][nt][2] + b0, 0.f);
                o.y = fmaxf(acc[mt][nt][3] + b1, 0.f);
                *(float2*)(C + (size_t)row1 * DIM + col) = o;
            }
        }
    }
}

extern "C" void kernel_launch(void* const* d_in, const int* in_sizes, int n_in,
                              void* d_out, int out_size) {
    const float* x   = (const float*)d_in[0];
    const float* Ws1 = (const float*)d_in[1];
    const float* bs1 = (const float*)d_in[2];
    const float* Ws2 = (const float*)d_in[3];
    const float* bs2 = (const float*)d_in[4];
    const void*  ei  = d_in[5];
    float* out = (float*)d_out;

    cudaFuncSetAttribute(gemm_mma, cudaFuncAttributeMaxDynamicSharedMemorySize, SMEM_GEMM);

    float *h_buf, *t_buf, *z_buf;
    cudaGetSymbolAddress((void**)&h_buf, g_h);
    cudaGetSymbolAddress((void**)&t_buf, g_t);
    cudaGetSymbolAddress((void**)&z_buf, g_z);

    const int edge_blocks = (N_EDGES + 255) / 256;          // 3125
    const int gemm_blocks = (N_NODES + 127) / 128;          // 391
    const int agg_blocks  = (N_NODES * 32 + 255) / 256;     // 6250

    // One-time preprocessing (edge_index and W reused by all layers)
    detect_idx_kernel<<<1, 32>>>((const int*)ei);
    zero_cnt_kernel<<<(N_NODES + 255) / 256, 256>>>();
    fill_kernel<<<edge_blocks, 256>>>(ei);
    convert_w_kernel<<<96, 256>>>(Ws1, Ws2);

    const float* zcur = x;
    for (int l = 0; l < NL; l++) {
        aggregate_kernel<<<agg_blocks, 256>>>(zcur, h_buf);
        gemm_mma<<<gemm_blocks, 256, SMEM_GEMM>>>(
            h_buf, 2 * l + 0, bs1 + (size_t)l * DIM, t_buf);
        float* zout = (l == NL - 1) ? out : z_buf;
        gemm_mma<<<gemm_blocks, 256, SMEM_GEMM>>>(
            t_buf, 2 * l + 1, bs2 + (size_t)l * DIM, zout);
        zcur = zout;
    }
}

// round 15
// speedup vs baseline: 1.2677x; 1.0307x over previous
#include <cuda_runtime.h>
#include <cuda_bf16.h>
#include <cstdint>

#define N_NODES 50000
#define N_EDGES 800000
#define DIM 128
#define NL 3
#define PAD 64      // max degree slack: P(Poisson(16) >= 64) ~ 1e-19 per node
#define STR 136     // padded bf16 row stride (136*2=272B -> conflict-free frags)
#define NROWPAD 50048   // 391 tiles * 128 rows

typedef unsigned long long u64;
typedef unsigned int u32;
typedef unsigned short us;

// Scratch (allocation-free rule: __device__ globals)
__device__ float g_z[(size_t)N_NODES * DIM];        // inter-layer fp32 activations
__device__ int   g_cnt[N_NODES];                    // per-dst degree counter
__device__ int   g_srcs[(size_t)N_NODES * PAD];     // padded CSR adjacency
__device__ int   g_is64;
// Split-bf16 activation images in padded [row][STR] layout (producer-written)
__device__ us g_hA_hi[(size_t)NROWPAD * STR];
__device__ us g_hA_lo[(size_t)NROWPAD * STR];
__device__ us g_tA_hi[(size_t)NROWPAD * STR];
__device__ us g_tA_lo[(size_t)NROWPAD * STR];
// Padded [n][k] bf16 images of W^T (hi/lo split), 6 matrices (3 layers x 2)
__device__ us g_Wimg_hi[6 * DIM * STR];
__device__ us g_Wimg_lo[6 * DIM * STR];

__device__ __forceinline__ void bsplit(float v, us& h, us& l) {
    __nv_bfloat16 bh = __float2bfloat16(v);
    float r = v - __bfloat162float(bh);
    __nv_bfloat16 bl = __float2bfloat16(r);
    h = __bfloat16_as_ushort(bh);
    l = __bfloat16_as_ushort(bl);
}

// mma.sync m16n8k16 row.col f32.bf16.bf16.f32 (sm_80+ PTX, tensor pipe)
__device__ __forceinline__ void mma16816(float c[4], const u32 a[4], u32 b0, u32 b1) {
    asm volatile(
        "mma.sync.aligned.m16n8k16.row.col.f32.bf16.bf16.f32 "
        "{%0,%1,%2,%3}, {%4,%5,%6,%7}, {%8,%9}, {%0,%1,%2,%3};"
        : "+f"(c[0]), "+f"(c[1]), "+f"(c[2]), "+f"(c[3])
        : "r"(a[0]), "r"(a[1]), "r"(a[2]), "r"(a[3]), "r"(b0), "r"(b1));
}

// ---------------------------------------------------------------------------
// Graph preprocessing
// ---------------------------------------------------------------------------
__global__ void detect_idx_kernel(const int* __restrict__ ei_i32) {
    const int lane = threadIdx.x;  // 32
    int bad = (ei_i32[2 * lane + 1] != 0) | (ei_i32[2 * (lane + 32) + 1] != 0);
    unsigned m = __ballot_sync(0xffffffffu, bad);
    if (lane == 0) g_is64 = (m == 0);
}

__global__ void zero_cnt_kernel() {
    int i = blockIdx.x * blockDim.x + threadIdx.x;
    if (i < N_NODES) g_cnt[i] = 0;
}

__global__ void fill_kernel(const void* __restrict__ ei) {
    int e = blockIdx.x * blockDim.x + threadIdx.x;
    if (e >= N_EDGES) return;
    int s, d;
    if (g_is64) {
        const long long* p = (const long long*)ei;
        s = (int)p[e];
        d = (int)p[N_EDGES + e];
    } else {
        const int* p = (const int*)ei;
        s = p[e];
        d = p[N_EDGES + e];
    }
    int slot = atomicAdd(&g_cnt[d], 1);
    if (slot < PAD) g_srcs[(size_t)d * PAD + slot] = s;
}

// Build padded bf16 hi/lo images of W^T: img[n][k] = W[k][n]. 96 blocks.
__global__ void convert_w_kernel(const float* __restrict__ Ws1,
                                 const float* __restrict__ Ws2) {
    const int mat = blockIdx.x >> 4;
    const int chunk = blockIdx.x & 15;
    const float* W = ((mat & 1) ? Ws2 : Ws1) + (size_t)(mat >> 1) * DIM * DIM;
    us* hi = g_Wimg_hi + (size_t)mat * DIM * STR;
    us* lo = g_Wimg_lo + (size_t)mat * DIM * STR;
    int idx = chunk * 1024 + threadIdx.x;
#pragma unroll
    for (int it = 0; it < 4; it++, idx += 256) {
        const int n = idx >> 7, k = idx & 127;
        us h, l;
        bsplit(W[k * DIM + n], h, l);
        hi[n * STR + k] = h;
        lo[n * STR + k] = l;
    }
}

// ---------------------------------------------------------------------------
// Aggregation: warp per node, h[n] = z[n] + sum_{s in adj(n)} z[s].
// Output written DIRECTLY as split-bf16 hi/lo in padded [row][STR] layout,
// so the GEMM staging becomes a pure memcpy. Split ALU hides under the
// L2-bound gather (issue was only 37%).
// ---------------------------------------------------------------------------
__global__ void aggregate_kernel(const float* __restrict__ z,
                                 us* __restrict__ out_hi,
                                 us* __restrict__ out_lo) {
    const int w = (blockIdx.x * blockDim.x + threadIdx.x) >> 5;
    if (w >= N_NODES) return;
    const int lane = threadIdx.x & 31;
    const float* zp = z + lane * 4;

    const int* adj = g_srcs + (size_t)w * PAD;
    int deg = g_cnt[w];
    if (deg > PAD) deg = PAD;

    float4 acc = *(const float4*)(zp + (size_t)w * DIM);  // self term
    int e = 0;
    for (; e + 4 <= deg; e += 4) {
        const int s0 = adj[e], s1 = adj[e + 1];
        const int s2 = adj[e + 2], s3 = adj[e + 3];
        const float4 v0 = *(const float4*)(zp + (size_t)s0 * DIM);
        const float4 v1 = *(const float4*)(zp + (size_t)s1 * DIM);
        const float4 v2 = *(const float4*)(zp + (size_t)s2 * DIM);
        const float4 v3 = *(const float4*)(zp + (size_t)s3 * DIM);
        acc.x += (v0.x + v1.x) + (v2.x + v3.x);
        acc.y += (v0.y + v1.y) + (v2.y + v3.y);
        acc.z += (v0.z + v1.z) + (v2.z + v3.z);
        acc.w += (v0.w + v1.w) + (v2.w + v3.w);
    }
    for (; e < deg; e++) {
        const float4 v = *(const float4*)(zp + (size_t)adj[e] * DIM);
        acc.x += v.x; acc.y += v.y; acc.z += v.z; acc.w += v.w;
    }

    us h0, h1, h2, h3, l0, l1, l2, l3;
    bsplit(acc.x, h0, l0); bsplit(acc.y, h1, l1);
    bsplit(acc.z, h2, l2); bsplit(acc.w, h3, l3);
    const size_t off = (size_t)w * STR + lane * 4;
    *(uint2*)(out_hi + off) = make_uint2((u32)h0 | ((u32)h1 << 16),
                                         (u32)h2 | ((u32)h3 << 16));
    *(uint2*)(out_lo + off) = make_uint2((u32)l0 | ((u32)l1 << 16),
                                         (u32)l2 | ((u32)l3 << 16));
}

// ---------------------------------------------------------------------------
// Tensor-pipe GEMM via mma.sync (bf16x3 split precision):
// C = relu(A @ W + bias), tile 128x128, full K=128.
// A arrives pre-split in padded layout -> staging is a pure uint4 memcpy.
// MODE 0: write fp32 C (guarded).  MODE 1: write split-bf16 C (padded imgs).
// ---------------------------------------------------------------------------
#define SMEM_GEMM (4 * 128 * STR * 2)   // Ah, Al, Wh, Wl = 139264 B

template <int MODE>
__global__ __launch_bounds__(256, 1)
void gemm_mma(const us* __restrict__ Ahi, const us* __restrict__ Alo, int mat,
              const float* __restrict__ bias,
              float* __restrict__ Cf,
              us* __restrict__ Chi, us* __restrict__ Clo) {
    extern __shared__ char smem[];
    us* sAh = (us*)smem;                 // [128][STR]
    us* sAl = sAh + 128 * STR;
    us* sWh = sAl + 128 * STR;
    us* sWl = sWh + 128 * STR;

    const int tid = threadIdx.x;   // 256
    const int wid = tid >> 5, lane = tid & 31;
    const int m0 = blockIdx.x * 128;

    // Pure memcpy staging: W images + pre-split A rows (all uint4, coalesced).
    {
        const uint4* wh = (const uint4*)(g_Wimg_hi + (size_t)mat * DIM * STR);
        const uint4* wl = (const uint4*)(g_Wimg_lo + (size_t)mat * DIM * STR);
        const uint4* ah = (const uint4*)(Ahi + (size_t)m0 * STR);
        const uint4* al = (const uint4*)(Alo + (size_t)m0 * STR);
        uint4* dwh = (uint4*)sWh;
        uint4* dwl = (uint4*)sWl;
        uint4* dah = (uint4*)sAh;
        uint4* dal = (uint4*)sAl;
        const int n16 = 128 * STR / 8;   // 2176 uint4 per image
#pragma unroll
        for (int it = 0; it < 9; it++) {
            const int i = tid + it * 256;
            if (i < n16) {
                dwh[i] = wh[i]; dwl[i] = wl[i];
                dah[i] = ah[i]; dal[i] = al[i];
            }
        }
    }
    __syncthreads();

    const int wm = wid & 3;    // 32-row group
    const int wn = wid >> 2;   // 64-col group
    const int g = lane >> 2, t = lane & 3;

    float acc[2][8][4];
#pragma unroll
    for (int mt = 0; mt < 2; mt++)
#pragma unroll
        for (int nt = 0; nt < 8; nt++)
#pragma unroll
            for (int r = 0; r < 4; r++) acc[mt][nt][r] = 0.f;

#pragma unroll
    for (int ks = 0; ks < 8; ks++) {
        const int k0 = ks * 16;
        u32 ah[2][4], al[2][4];
#pragma unroll
        for (int mt = 0; mt < 2; mt++) {
            const int base = (wm * 32 + mt * 16 + g) * STR + k0 + t * 2;
            ah[mt][0] = *(const u32*)(sAh + base);
            ah[mt][1] = *(const u32*)(sAh + base + 8 * STR);
            ah[mt][2] = *(const u32*)(sAh + base + 8);
            ah[mt][3] = *(const u32*)(sAh + base + 8 * STR + 8);
            al[mt][0] = *(const u32*)(sAl + base);
            al[mt][1] = *(const u32*)(sAl + base + 8 * STR);
            al[mt][2] = *(const u32*)(sAl + base + 8);
            al[mt][3] = *(const u32*)(sAl + base + 8 * STR + 8);
        }
#pragma unroll
        for (int nt = 0; nt < 8; nt++) {
            const int bbase = (wn * 64 + nt * 8 + g) * STR + k0 + t * 2;
            const u32 bh0 = *(const u32*)(sWh + bbase);
            const u32 bh1 = *(const u32*)(sWh + bbase + 8);
            const u32 bl0 = *(const u32*)(sWl + bbase);
            const u32 bl1 = *(const u32*)(sWl + bbase + 8);
#pragma unroll
            for (int mt = 0; mt < 2; mt++) {
                mma16816(acc[mt][nt], ah[mt], bh0, bh1);
                mma16816(acc[mt][nt], ah[mt], bl0, bl1);
                mma16816(acc[mt][nt], al[mt], bh0, bh1);
            }
        }
    }

    // Epilogue: bias + relu.
#pragma unroll
    for (int nt = 0; nt < 8; nt++) {
        const int col = wn * 64 + nt * 8 + t * 2;
        const float b0 = bias[col], b1 = bias[col + 1];
#pragma unroll
        for (int mt = 0; mt < 2; mt++) {
            const int lrow0 = wm * 32 + mt * 16 + g;   // local rows
            const int row0 = m0 + lrow0;
            const int row1 = row0 + 8;
            const float v00 = fmaxf(acc[mt][nt][0] + b0, 0.f);
            const float v01 = fmaxf(acc[mt][nt][1] + b1, 0.f);
            const float v10 = fmaxf(acc[mt][nt][2] + b0, 0.f);
            const float v11 = fmaxf(acc[mt][nt][3] + b1, 0.f);
            if (MODE == 0) {
                if (row0 < N_NODES) {
                    float2 o; o.x = v00; o.y = v01;
                    *(float2*)(Cf + (size_t)row0 * DIM + col) = o;
                }
                if (row1 < N_NODES) {
                    float2 o; o.x = v10; o.y = v11;
                    *(float2*)(Cf + (size_t)row1 * DIM + col) = o;
                }
            } else {
                us h0, l0, h1, l1, h2, l2, h3, l3;
                bsplit(v00, h0, l0); bsplit(v01, h1, l1);
                bsplit(v10, h2, l2); bsplit(v11, h3, l3);
                *(u32*)(Chi + (size_t)row0 * STR + col) = (u32)h0 | ((u32)h1 << 16);
                *(u32*)(Clo + (size_t)row0 * STR + col) = (u32)l0 | ((u32)l1 << 16);
                *(u32*)(Chi + (size_t)row1 * STR + col) = (u32)h2 | ((u32)h3 << 16);
                *(u32*)(Clo + (size_t)row1 * STR + col) = (u32)l2 | ((u32)l3 << 16);
            }
        }
    }
}

extern "C" void kernel_launch(void* const* d_in, const int* in_sizes, int n_in,
                              void* d_out, int out_size) {
    const float* x   = (const float*)d_in[0];
    const float* Ws1 = (const float*)d_in[1];
    const float* bs1 = (const float*)d_in[2];
    const float* Ws2 = (const float*)d_in[3];
    const float* bs2 = (const float*)d_in[4];
    const void*  ei  = d_in[5];
    float* out = (float*)d_out;

    cudaFuncSetAttribute(gemm_mma<0>, cudaFuncAttributeMaxDynamicSharedMemorySize,
                         SMEM_GEMM);
    cudaFuncSetAttribute(gemm_mma<1>, cudaFuncAttributeMaxDynamicSharedMemorySize,
                         SMEM_GEMM);

    float* z_buf;
    us *hA_hi, *hA_lo, *tA_hi, *tA_lo;
    cudaGetSymbolAddress((void**)&z_buf, g_z);
    cudaGetSymbolAddress((void**)&hA_hi, g_hA_hi);
    cudaGetSymbolAddress((void**)&hA_lo, g_hA_lo);
    cudaGetSymbolAddress((void**)&tA_hi, g_tA_hi);
    cudaGetSymbolAddress((void**)&tA_lo, g_tA_lo);

    const int edge_blocks = (N_EDGES + 255) / 256;          // 3125
    const int gemm_blocks = (N_NODES + 127) / 128;          // 391
    const int agg_blocks  = (N_NODES * 32 + 255) / 256;     // 6250

    // One-time preprocessing (edge_index and W reused by all layers)
    detect_idx_kernel<<<1, 32>>>((const int*)ei);
    zero_cnt_kernel<<<(N_NODES + 255) / 256, 256>>>();
    fill_kernel<<<edge_blocks, 256>>>(ei);
    convert_w_kernel<<<96, 256>>>(Ws1, Ws2);

    const float* zcur = x;
    for (int l = 0; l < NL; l++) {
        aggregate_kernel<<<agg_blocks, 256>>>(zcur, hA_hi, hA_lo);
        // GEMM1: t = relu(h@W1+b1), written as split-bf16 images
        gemm_mma<1><<<gemm_blocks, 256, SMEM_GEMM>>>(
            hA_hi, hA_lo, 2 * l + 0, bs1 + (size_t)l * DIM,
            nullptr, tA_hi, tA_lo);
        // GEMM2: z = relu(t@W2+b2), fp32 (next aggregate / final out)
        float* zout = (l == NL - 1) ? out : z_buf;
        gemm_mma<0><<<gemm_blocks, 256, SMEM_GEMM>>>(
            tA_hi, tA_lo, 2 * l + 1, bs2 + (size_t)l * DIM,
            zout, nullptr, nullptr);
        zcur = zout;
    }
}

// round 16
// speedup vs baseline: 1.3041x; 1.0287x over previous
#include <cuda_runtime.h>
#include <cuda_bf16.h>
#include <cstdint>

#define N_NODES 50000
#define N_EDGES 800000
#define DIM 128
#define NL 3
#define PAD 64      // max degree slack: P(Poisson(16) >= 64) ~ 1e-19 per node
#define STR 136     // padded bf16 row stride (136*2=272B -> conflict-free frags)
#define NROWPAD 50048   // 782 tiles * 64 rows

typedef unsigned long long u64;
typedef unsigned int u32;
typedef unsigned short us;

// Scratch (allocation-free rule: __device__ globals)
__device__ float g_z[(size_t)N_NODES * DIM];        // inter-layer fp32 activations
__device__ int   g_cnt[N_NODES];                    // per-dst degree counter
__device__ int   g_srcs[(size_t)N_NODES * PAD];     // padded CSR adjacency
__device__ int   g_is64;
// Split-bf16 activation images in padded [row][STR] layout (producer-written)
__device__ us g_hA_hi[(size_t)NROWPAD * STR];
__device__ us g_hA_lo[(size_t)NROWPAD * STR];
__device__ us g_tA_hi[(size_t)NROWPAD * STR];
__device__ us g_tA_lo[(size_t)NROWPAD * STR];
// Padded [n][k] bf16 images of W^T (hi/lo split), 6 matrices (3 layers x 2)
__device__ us g_Wimg_hi[6 * DIM * STR];
__device__ us g_Wimg_lo[6 * DIM * STR];

__device__ __forceinline__ void bsplit(float v, us& h, us& l) {
    __nv_bfloat16 bh = __float2bfloat16(v);
    float r = v - __bfloat162float(bh);
    __nv_bfloat16 bl = __float2bfloat16(r);
    h = __bfloat16_as_ushort(bh);
    l = __bfloat16_as_ushort(bl);
}

// mma.sync m16n8k16 row.col f32.bf16.bf16.f32 (sm_80+ PTX, tensor pipe)
__device__ __forceinline__ void mma16816(float c[4], const u32 a[4], u32 b0, u32 b1) {
    asm volatile(
        "mma.sync.aligned.m16n8k16.row.col.f32.bf16.bf16.f32 "
        "{%0,%1,%2,%3}, {%4,%5,%6,%7}, {%8,%9}, {%0,%1,%2,%3};"
        : "+f"(c[0]), "+f"(c[1]), "+f"(c[2]), "+f"(c[3])
        : "r"(a[0]), "r"(a[1]), "r"(a[2]), "r"(a[3]), "r"(b0), "r"(b1));
}

// ---------------------------------------------------------------------------
// Graph preprocessing
// ---------------------------------------------------------------------------
__global__ void detect_idx_kernel(const int* __restrict__ ei_i32) {
    const int lane = threadIdx.x;  // 32
    int bad = (ei_i32[2 * lane + 1] != 0) | (ei_i32[2 * (lane + 32) + 1] != 0);
    unsigned m = __ballot_sync(0xffffffffu, bad);
    if (lane == 0) g_is64 = (m == 0);
}

__global__ void zero_cnt_kernel() {
    int i = blockIdx.x * blockDim.x + threadIdx.x;
    if (i < N_NODES) g_cnt[i] = 0;
}

__global__ void fill_kernel(const void* __restrict__ ei) {
    int e = blockIdx.x * blockDim.x + threadIdx.x;
    if (e >= N_EDGES) return;
    int s, d;
    if (g_is64) {
        const long long* p = (const long long*)ei;
        s = (int)p[e];
        d = (int)p[N_EDGES + e];
    } else {
        const int* p = (const int*)ei;
        s = p[e];
        d = p[N_EDGES + e];
    }
    int slot = atomicAdd(&g_cnt[d], 1);
    if (slot < PAD) g_srcs[(size_t)d * PAD + slot] = s;
}

// Build padded bf16 hi/lo images of W^T: img[n][k] = W[k][n].
// 384 blocks x 256 threads: one element per thread (latency-bound fix).
__global__ void convert_w_kernel(const float* __restrict__ Ws1,
                                 const float* __restrict__ Ws2) {
    const int mat = blockIdx.x >> 6;          // 0..5
    const int chunk = blockIdx.x & 63;        // 0..63
    const float* W = ((mat & 1) ? Ws2 : Ws1) + (size_t)(mat >> 1) * DIM * DIM;
    us* hi = g_Wimg_hi + (size_t)mat * DIM * STR;
    us* lo = g_Wimg_lo + (size_t)mat * DIM * STR;
    const int idx = chunk * 256 + threadIdx.x;   // 0..16383
    const int n = idx >> 7, k = idx & 127;
    us h, l;
    bsplit(W[k * DIM + n], h, l);
    hi[n * STR + k] = h;
    lo[n * STR + k] = l;
}

// ---------------------------------------------------------------------------
// Aggregation: warp per node, h[n] = z[n] + sum_{s in adj(n)} z[s].
// Output written DIRECTLY as split-bf16 hi/lo in padded [row][STR] layout.
// ---------------------------------------------------------------------------
__global__ void aggregate_kernel(const float* __restrict__ z,
                                 us* __restrict__ out_hi,
                                 us* __restrict__ out_lo) {
    const int w = (blockIdx.x * blockDim.x + threadIdx.x) >> 5;
    if (w >= N_NODES) return;
    const int lane = threadIdx.x & 31;
    const float* zp = z + lane * 4;

    const int* adj = g_srcs + (size_t)w * PAD;
    int deg = g_cnt[w];
    if (deg > PAD) deg = PAD;

    float4 acc = *(const float4*)(zp + (size_t)w * DIM);  // self term
    int e = 0;
    for (; e + 4 <= deg; e += 4) {
        const int s0 = adj[e], s1 = adj[e + 1];
        const int s2 = adj[e + 2], s3 = adj[e + 3];
        const float4 v0 = *(const float4*)(zp + (size_t)s0 * DIM);
        const float4 v1 = *(const float4*)(zp + (size_t)s1 * DIM);
        const float4 v2 = *(const float4*)(zp + (size_t)s2 * DIM);
        const float4 v3 = *(const float4*)(zp + (size_t)s3 * DIM);
        acc.x += (v0.x + v1.x) + (v2.x + v3.x);
        acc.y += (v0.y + v1.y) + (v2.y + v3.y);
        acc.z += (v0.z + v1.z) + (v2.z + v3.z);
        acc.w += (v0.w + v1.w) + (v2.w + v3.w);
    }
    for (; e < deg; e++) {
        const float4 v = *(const float4*)(zp + (size_t)adj[e] * DIM);
        acc.x += v.x; acc.y += v.y; acc.z += v.z; acc.w += v.w;
    }

    us h0, h1, h2, h3, l0, l1, l2, l3;
    bsplit(acc.x, h0, l0); bsplit(acc.y, h1, l1);
    bsplit(acc.z, h2, l2); bsplit(acc.w, h3, l3);
    const size_t off = (size_t)w * STR + lane * 4;
    *(uint2*)(out_hi + off) = make_uint2((u32)h0 | ((u32)h1 << 16),
                                         (u32)h2 | ((u32)h3 << 16));
    *(uint2*)(out_lo + off) = make_uint2((u32)l0 | ((u32)l1 << 16),
                                         (u32)l2 | ((u32)l3 << 16));
}

// ---------------------------------------------------------------------------
// Tensor-pipe GEMM via mma.sync (bf16x3 split precision):
// C = relu(A @ W + bias), 64-row tile x full 128 cols, K=128.
// smem = 102KB -> 2 CTAs/SM (16 warps) so staging overlaps compute.
// 8 warps: 2m x 4n, warp tile 32x32 (2x4 m16n8k16).
// MODE 0: fp32 C (guarded).  MODE 1: split-bf16 C (padded images).
// ---------------------------------------------------------------------------
#define SMEM_GEMM (2 * 64 * STR * 2 + 2 * 128 * STR * 2)   // 104448 B

template <int MODE>
__global__ __launch_bounds__(256, 2)
void gemm_mma(const us* __restrict__ Ahi, const us* __restrict__ Alo, int mat,
              const float* __restrict__ bias,
              float* __restrict__ Cf,
              us* __restrict__ Chi, us* __restrict__ Clo) {
    extern __shared__ char smem[];
    us* sAh = (us*)smem;                 // [64][STR]
    us* sAl = sAh + 64 * STR;
    us* sWh = sAl + 64 * STR;            // [128][STR]
    us* sWl = sWh + 128 * STR;

    const int tid = threadIdx.x;   // 256
    const int wid = tid >> 5, lane = tid & 31;
    const int m0 = blockIdx.x * 64;

    // Pure memcpy staging (uint4, coalesced): W 2x2176, A 2x1088.
    {
        const uint4* wh = (const uint4*)(g_Wimg_hi + (size_t)mat * DIM * STR);
        const uint4* wl = (const uint4*)(g_Wimg_lo + (size_t)mat * DIM * STR);
        const uint4* ah = (const uint4*)(Ahi + (size_t)m0 * STR);
        const uint4* al = (const uint4*)(Alo + (size_t)m0 * STR);
        uint4* dwh = (uint4*)sWh;
        uint4* dwl = (uint4*)sWl;
        uint4* dah = (uint4*)sAh;
        uint4* dal = (uint4*)sAl;
#pragma unroll
        for (int it = 0; it < 9; it++) {          // 2176 = 8.5 * 256
            const int i = tid + it * 256;
            if (i < 128 * STR / 8) { dwh[i] = wh[i]; dwl[i] = wl[i]; }
        }
#pragma unroll
        for (int it = 0; it < 5; it++) {          // 1088 = 4.25 * 256
            const int i = tid + it * 256;
            if (i < 64 * STR / 8) { dah[i] = ah[i]; dal[i] = al[i]; }
        }
    }
    __syncthreads();

    const int wm = wid & 1;    // 32-row group (0..1)
    const int wn = wid >> 1;   // 32-col group (0..3)
    const int g = lane >> 2, t = lane & 3;

    float acc[2][4][4];
#pragma unroll
    for (int mt = 0; mt < 2; mt++)
#pragma unroll
        for (int nt = 0; nt < 4; nt++)
#pragma unroll
            for (int r = 0; r < 4; r++) acc[mt][nt][r] = 0.f;

#pragma unroll
    for (int ks = 0; ks < 8; ks++) {
        const int k0 = ks * 16;
        u32 ah[2][4], al[2][4];
#pragma unroll
        for (int mt = 0; mt < 2; mt++) {
            const int base = (wm * 32 + mt * 16 + g) * STR + k0 + t * 2;
            ah[mt][0] = *(const u32*)(sAh + base);
            ah[mt][1] = *(const u32*)(sAh + base + 8 * STR);
            ah[mt][2] = *(const u32*)(sAh + base + 8);
            ah[mt][3] = *(const u32*)(sAh + base + 8 * STR + 8);
            al[mt][0] = *(const u32*)(sAl + base);
            al[mt][1] = *(const u32*)(sAl + base + 8 * STR);
            al[mt][2] = *(const u32*)(sAl + base + 8);
            al[mt][3] = *(const u32*)(sAl + base + 8 * STR + 8);
        }
#pragma unroll
        for (int nt = 0; nt < 4; nt++) {
            const int bbase = (wn * 32 + nt * 8 + g) * STR + k0 + t * 2;
            const u32 bh0 = *(const u32*)(sWh + bbase);
            const u32 bh1 = *(const u32*)(sWh + bbase + 8);
            const u32 bl0 = *(const u32*)(sWl + bbase);
            const u32 bl1 = *(const u32*)(sWl + bbase + 8);
#pragma unroll
            for (int mt = 0; mt < 2; mt++) {
                mma16816(acc[mt][nt], ah[mt], bh0, bh1);
                mma16816(acc[mt][nt], ah[mt], bl0, bl1);
                mma16816(acc[mt][nt], al[mt], bh0, bh1);
            }
        }
    }

    // Epilogue: bias + relu.
#pragma unroll
    for (int nt = 0; nt < 4; nt++) {
        const int col = wn * 32 + nt * 8 + t * 2;
        const float b0 = bias[col], b1 = bias[col + 1];
#pragma unroll
        for (int mt = 0; mt < 2; mt++) {
            const int row0 = m0 + wm * 32 + mt * 16 + g;
            const int row1 = row0 + 8;
            const float v00 = fmaxf(acc[mt][nt][0] + b0, 0.f);
            const float v01 = fmaxf(acc[mt][nt][1] + b1, 0.f);
            const float v10 = fmaxf(acc[mt][nt][2] + b0, 0.f);
            const float v11 = fmaxf(acc[mt][nt][3] + b1, 0.f);
            if (MODE == 0) {
                if (row0 < N_NODES) {
                    float2 o; o.x = v00; o.y = v01;
                    *(float2*)(Cf + (size_t)row0 * DIM + col) = o;
                }
                if (row1 < N_NODES) {
                    float2 o; o.x = v10; o.y = v11;
                    *(float2*)(Cf + (size_t)row1 * DIM + col) = o;
                }
            } else {
                us h0, l0, h1, l1, h2, l2, h3, l3;
                bsplit(v00, h0, l0); bsplit(v01, h1, l1);
                bsplit(v10, h2, l2); bsplit(v11, h3, l3);
                *(u32*)(Chi + (size_t)row0 * STR + col) = (u32)h0 | ((u32)h1 << 16);
                *(u32*)(Clo + (size_t)row0 * STR + col) = (u32)l0 | ((u32)l1 << 16);
                *(u32*)(Chi + (size_t)row1 * STR + col) = (u32)h2 | ((u32)h3 << 16);
                *(u32*)(Clo + (size_t)row1 * STR + col) = (u32)l2 | ((u32)l3 << 16);
            }
        }
    }
}

extern "C" void kernel_launch(void* const* d_in, const int* in_sizes, int n_in,
                              void* d_out, int out_size) {
    const float* x   = (const float*)d_in[0];
    const float* Ws1 = (const float*)d_in[1];
    const float* bs1 = (const float*)d_in[2];
    const float* Ws2 = (const float*)d_in[3];
    const float* bs2 = (const float*)d_in[4];
    const void*  ei  = d_in[5];
    float* out = (float*)d_out;

    cudaFuncSetAttribute(gemm_mma<0>, cudaFuncAttributeMaxDynamicSharedMemorySize,
                         SMEM_GEMM);
    cudaFuncSetAttribute(gemm_mma<1>, cudaFuncAttributeMaxDynamicSharedMemorySize,
                         SMEM_GEMM);

    float* z_buf;
    us *hA_hi, *hA_lo, *tA_hi, *tA_lo;
    cudaGetSymbolAddress((void**)&z_buf, g_z);
    cudaGetSymbolAddress((void**)&hA_hi, g_hA_hi);
    cudaGetSymbolAddress((void**)&hA_lo, g_hA_lo);
    cudaGetSymbolAddress((void**)&tA_hi, g_tA_hi);
    cudaGetSymbolAddress((void**)&tA_lo, g_tA_lo);

    const int edge_blocks = (N_EDGES + 255) / 256;          // 3125
    const int gemm_blocks = (N_NODES + 63) / 64;            // 782
    const int agg_blocks  = (N_NODES * 32 + 255) / 256;     // 6250

    // One-time preprocessing (edge_index and W reused by all layers)
    detect_idx_kernel<<<1, 32>>>((const int*)ei);
    zero_cnt_kernel<<<(N_NODES + 255) / 256, 256>>>();
    fill_kernel<<<edge_blocks, 256>>>(ei);
    convert_w_kernel<<<384, 256>>>(Ws1, Ws2);

    const float* zcur = x;
    for (int l = 0; l < NL; l++) {
        aggregate_kernel<<<agg_blocks, 256>>>(zcur, hA_hi, hA_lo);
        // GEMM1: t = relu(h@W1+b1), written as split-bf16 images
        gemm_mma<1><<<gemm_blocks, 256, SMEM_GEMM>>>(
            hA_hi, hA_lo, 2 * l + 0, bs1 + (size_t)l * DIM,
            nullptr, tA_hi, tA_lo);
        // GEMM2: z = relu(t@W2+b2), fp32 (next aggregate / final out)
        float* zout = (l == NL - 1) ? out : z_buf;
        gemm_mma<0><<<gemm_blocks, 256, SMEM_GEMM>>>(
            tA_hi, tA_lo, 2 * l + 1, bs2 + (size_t)l * DIM,
            zout, nullptr, nullptr);
        zcur = zout;
    }
}